// round 1
// baseline (speedup 1.0000x reference)
#include <cuda_runtime.h>
#include <math_constants.h>

// Banded sparse attention, B=256, S=128, D_MODEL=1024, H=16, Dh=64, |i-j|<=4.
// One CTA per (batch, head, 64-query tile). Band of k/v rows staged in smem.
// Half-warp (16 lanes x float4) per query: 4-step shfl reduction for dots.

#define BATCH 256
#define SEQ   128
#define DMODEL 1024
#define NHEADS 16
#define HEADD 64
#define HW 4            // band half width
#define BANDW 9         // 2*HW+1
#define QT 64           // queries per block
#define ROWS (QT + 2*HW) // 72 staged k/v rows
#define SCALE 0.125f    // 64^-0.5

__global__ __launch_bounds__(1024, 2)
void banded_attn_kernel(const float* __restrict__ q,
                        const float* __restrict__ k,
                        const float* __restrict__ v,
                        float* __restrict__ out)
{
    __shared__ float ks[ROWS][HEADD];
    __shared__ float vs[ROWS][HEADD];

    const int b  = blockIdx.z;
    const int h  = blockIdx.y;
    const int q0 = blockIdx.x * QT;
    const int j0 = q0 - HW;              // first band row (may be negative)
    const int tid = threadIdx.x;

    const size_t base = ((size_t)b * SEQ) * DMODEL + (size_t)h * HEADD;

    // ---- Stage k/v band into smem (float4, coalesced; zero-fill OOB rows) ----
    for (int idx = tid; idx < ROWS * (HEADD / 4); idx += blockDim.x) {
        const int r = idx >> 4;          // row 0..71
        const int c = idx & 15;          // float4 index 0..15
        const int j = j0 + r;
        float4 kv = make_float4(0.f, 0.f, 0.f, 0.f);
        float4 vv = kv;
        if (j >= 0 && j < SEQ) {
            const size_t off = base + (size_t)j * DMODEL;
            kv = ((const float4*)(k + off))[c];
            vv = ((const float4*)(v + off))[c];
        }
        *(float4*)&ks[r][c * 4] = kv;
        *(float4*)&vs[r][c * 4] = vv;
    }
    __syncthreads();

    // ---- Half-warp per query ----
    const int warp = tid >> 5;
    const int lane = tid & 31;
    const int half = lane >> 4;          // 0/1: which query of this warp
    const int sub  = lane & 15;          // lane within the 16-lane group
    const int i    = q0 + (warp << 1) + half;   // global query index
    const int rbase = i - q0;            // smem row of j = i-HW  (in [0,63])

    // q row: 4 dims per lane
    const float4 qv = ((const float4*)(q + base + (size_t)i * DMODEL))[sub];

    float s[BANDW];
#pragma unroll
    for (int o = 0; o < BANDW; ++o) {
        const float4 kv = *(const float4*)&ks[rbase + o][sub * 4];
        float d = qv.x * kv.x + qv.y * kv.y + qv.z * kv.z + qv.w * kv.w;
        d += __shfl_xor_sync(0xffffffffu, d, 1);
        d += __shfl_xor_sync(0xffffffffu, d, 2);
        d += __shfl_xor_sync(0xffffffffu, d, 4);
        d += __shfl_xor_sync(0xffffffffu, d, 8);
        s[o] = d * SCALE;
    }

    // Mask invalid band positions, softmax over <=9 entries
    float m = -CUDART_INF_F;
#pragma unroll
    for (int o = 0; o < BANDW; ++o) {
        const int j = i - HW + o;
        if (j < 0 || j >= SEQ) s[o] = -CUDART_INF_F;
        m = fmaxf(m, s[o]);
    }
    float sum = 0.f;
#pragma unroll
    for (int o = 0; o < BANDW; ++o) {
        s[o] = __expf(s[o] - m);
        sum += s[o];
    }
    const float inv = 1.0f / sum;

    float4 acc = make_float4(0.f, 0.f, 0.f, 0.f);
#pragma unroll
    for (int o = 0; o < BANDW; ++o) {
        const float w = s[o] * inv;
        const float4 vv = *(const float4*)&vs[rbase + o][sub * 4];
        acc.x += w * vv.x;
        acc.y += w * vv.y;
        acc.z += w * vv.z;
        acc.w += w * vv.w;
    }

    ((float4*)(out + base + (size_t)i * DMODEL))[sub] = acc;
}

extern "C" void kernel_launch(void* const* d_in, const int* in_sizes, int n_in,
                              void* d_out, int out_size)
{
    const float* q = (const float*)d_in[0];
    const float* k = (const float*)d_in[1];
    const float* v = (const float*)d_in[2];
    float* out = (float*)d_out;

    dim3 grid(SEQ / QT, NHEADS, BATCH);   // (2, 16, 256)
    dim3 block(1024);
    banded_attn_kernel<<<grid, block>>>(q, k, v, out);
}

// round 2
// speedup vs baseline: 1.8796x; 1.8796x over previous
#include <cuda_runtime.h>
#include <math_constants.h>

// Banded sparse attention, B=256, S=128, D=1024, H=16, Dh=64, |i-j|<=4.
// One CTA per (batch, head, 64-query tile). k/v band staged in smem.
// 4-lane group handles 2 consecutive queries (shared 10-row band):
//  - 2-shfl dot reductions (vs 4), one shfl serves 8 groups/warp
//  - each k/v row read once per group, used by both queries
// smem row stride 72 floats => conflict-free LDS.128 phases.

#define SEQ    128
#define DMODEL 1024
#define NHEADS 16
#define HEADD  64
#define HW     4
#define BANDW  9
#define QT     64
#define ROWS   (QT + 2*HW)   // 72
#define RSTR   72            // row stride in floats (8 mod 16 -> phase-disjoint banks)
#define SCALE  0.125f

__global__ __launch_bounds__(128, 5)
void banded_attn_kernel(const float* __restrict__ q,
                        const float* __restrict__ k,
                        const float* __restrict__ v,
                        float* __restrict__ out)
{
    __shared__ float ks[ROWS * RSTR];
    __shared__ float vs[ROWS * RSTR];

    const int b   = blockIdx.z;
    const int h   = blockIdx.y;
    const int q0  = blockIdx.x * QT;
    const int j0  = q0 - HW;
    const int tid = threadIdx.x;

    const size_t base = ((size_t)b * SEQ) * DMODEL + (size_t)h * HEADD;

    // ---- Stage k/v band (coalesced float4; zero-fill OOB rows) ----
    for (int idx = tid; idx < ROWS * (HEADD / 4); idx += 128) {
        const int r = idx >> 4;          // row 0..71
        const int c = idx & 15;          // float4 col
        const int j = j0 + r;
        float4 kv = make_float4(0.f, 0.f, 0.f, 0.f);
        float4 vv = kv;
        if (j >= 0 && j < SEQ) {
            const size_t off = base + (size_t)j * DMODEL;
            kv = ((const float4*)(k + off))[c];
            vv = ((const float4*)(v + off))[c];
        }
        *(float4*)&ks[r * RSTR + c * 4] = kv;
        *(float4*)&vs[r * RSTR + c * 4] = vv;
    }
    __syncthreads();

    // ---- 4-lane group per 2 consecutive queries ----
    const int g   = tid >> 2;            // group 0..31
    const int s   = tid & 3;             // sub-lane: owns float4 indices s, s+4, s+8, s+12
    const int i0l = g * 2;               // local query indices i0l, i0l+1
    const int i0  = q0 + i0l;
    const int i1  = i0 + 1;

    // Load both q rows (16 dims per lane, 4x float4, 64B-contiguous per group)
    float4 qv0[4], qv1[4];
#pragma unroll
    for (int c = 0; c < 4; ++c) {
        qv0[c] = ((const float4*)(q + base + (size_t)i0 * DMODEL))[s + 4 * c];
        qv1[c] = ((const float4*)(q + base + (size_t)i1 * DMODEL))[s + 4 * c];
    }

    // ---- Score partials: 10 shared rows serve both queries ----
    float p0[10], p1[10];
#pragma unroll
    for (int t = 0; t < 10; ++t) {
        const float* krow = &ks[(i0l + t) * RSTR];
        float d0 = 0.f, d1 = 0.f;
#pragma unroll
        for (int c = 0; c < 4; ++c) {
            const float4 kc = *(const float4*)&krow[4 * (s + 4 * c)];
            if (t < 9) {
                d0 += qv0[c].x * kc.x + qv0[c].y * kc.y
                    + qv0[c].z * kc.z + qv0[c].w * kc.w;
            }
            if (t > 0) {
                d1 += qv1[c].x * kc.x + qv1[c].y * kc.y
                    + qv1[c].z * kc.z + qv1[c].w * kc.w;
            }
        }
        p0[t] = d0;
        p1[t] = d1;
    }

    // ---- Reduce within 4-lane group (2 shfl per score), mask, softmax ----
    float w0[BANDW], w1[BANDW];
#pragma unroll
    for (int o = 0; o < BANDW; ++o) {
        float d0 = p0[o];
        d0 += __shfl_xor_sync(0xffffffffu, d0, 1);
        d0 += __shfl_xor_sync(0xffffffffu, d0, 2);
        float d1 = p1[o + 1];
        d1 += __shfl_xor_sync(0xffffffffu, d1, 1);
        d1 += __shfl_xor_sync(0xffffffffu, d1, 2);
        const int ja = i0 - HW + o;
        const int jb = i1 - HW + o;
        w0[o] = (ja >= 0 && ja < SEQ) ? d0 * SCALE : -CUDART_INF_F;
        w1[o] = (jb >= 0 && jb < SEQ) ? d1 * SCALE : -CUDART_INF_F;
    }

    float m0 = -CUDART_INF_F, m1 = -CUDART_INF_F;
#pragma unroll
    for (int o = 0; o < BANDW; ++o) { m0 = fmaxf(m0, w0[o]); m1 = fmaxf(m1, w1[o]); }
    float sum0 = 0.f, sum1 = 0.f;
#pragma unroll
    for (int o = 0; o < BANDW; ++o) {
        w0[o] = __expf(w0[o] - m0); sum0 += w0[o];
        w1[o] = __expf(w1[o] - m1); sum1 += w1[o];
    }
    const float inv0 = 1.0f / sum0;
    const float inv1 = 1.0f / sum1;
#pragma unroll
    for (int o = 0; o < BANDW; ++o) { w0[o] *= inv0; w1[o] *= inv1; }

    // ---- Weighted V: 10 shared rows serve both accumulators ----
    float4 a0[4], a1[4];
#pragma unroll
    for (int c = 0; c < 4; ++c) {
        a0[c] = make_float4(0.f, 0.f, 0.f, 0.f);
        a1[c] = make_float4(0.f, 0.f, 0.f, 0.f);
    }
#pragma unroll
    for (int t = 0; t < 10; ++t) {
        const float* vrow = &vs[(i0l + t) * RSTR];
#pragma unroll
        for (int c = 0; c < 4; ++c) {
            const float4 vc = *(const float4*)&vrow[4 * (s + 4 * c)];
            if (t < 9) {
                const float w = w0[t];
                a0[c].x += w * vc.x; a0[c].y += w * vc.y;
                a0[c].z += w * vc.z; a0[c].w += w * vc.w;
            }
            if (t > 0) {
                const float w = w1[t - 1];
                a1[c].x += w * vc.x; a1[c].y += w * vc.y;
                a1[c].z += w * vc.z; a1[c].w += w * vc.w;
            }
        }
    }

#pragma unroll
    for (int c = 0; c < 4; ++c) {
        ((float4*)(out + base + (size_t)i0 * DMODEL))[s + 4 * c] = a0[c];
        ((float4*)(out + base + (size_t)i1 * DMODEL))[s + 4 * c] = a1[c];
    }
}

extern "C" void kernel_launch(void* const* d_in, const int* in_sizes, int n_in,
                              void* d_out, int out_size)
{
    const float* q = (const float*)d_in[0];
    const float* k = (const float*)d_in[1];
    const float* v = (const float*)d_in[2];
    float* out = (float*)d_out;

    dim3 grid(SEQ / QT, NHEADS, 256);   // (2, 16, 256)
    dim3 block(128);
    banded_attn_kernel<<<grid, block>>>(q, k, v, out);
}

// round 3
// speedup vs baseline: 2.2197x; 1.1810x over previous
#include <cuda_runtime.h>
#include <math_constants.h>

// Banded sparse attention, B=256, S=128, D=1024, H=16, Dh=64, |i-j|<=4.
// No smem: k/v band rows are L1-cached and reused by neighboring groups.
// 8-lane group handles 2 consecutive queries (shared 10-row band).
// Each lane owns 8 dims (2 float4, 32B contiguous). 3-shfl reductions.

#define SEQ    128
#define DMODEL 1024
#define NHEADS 16
#define HEADD  64
#define HW     4
#define BANDW  9
#define QT     64
#define SCALE  0.125f

__device__ __forceinline__ float dot4(const float4 a, const float4 b) {
    return a.x * b.x + a.y * b.y + a.z * b.z + a.w * b.w;
}

__global__ __launch_bounds__(256, 4)
void banded_attn_kernel(const float* __restrict__ q,
                        const float* __restrict__ k,
                        const float* __restrict__ v,
                        float* __restrict__ out)
{
    const int b   = blockIdx.z;
    const int h   = blockIdx.y;
    const int q0  = blockIdx.x * QT;
    const int j0  = q0 - HW;
    const int tid = threadIdx.x;

    const int g   = tid >> 3;          // group 0..31
    const int s   = tid & 7;           // lane in group; owns float4 cols 2s, 2s+1
    const int i0l = g * 2;
    const int i0  = q0 + i0l;          // query 0
    const int i1  = i0 + 1;            // query 1

    const size_t base = ((size_t)b * SEQ) * DMODEL + (size_t)h * HEADD;

    // q rows for both queries: 8 dims per lane each
    const float4* q0p = (const float4*)(q + base + (size_t)i0 * DMODEL);
    const float4* q1p = (const float4*)(q + base + (size_t)i1 * DMODEL);
    const float4 qa0 = q0p[2 * s],  qa1 = q0p[2 * s + 1];
    const float4 qb0 = q1p[2 * s],  qb1 = q1p[2 * s + 1];

    // ---- Scores: 10 shared k rows serve both queries; inline 3-shfl reduce ----
    float w0[BANDW], w1[BANDW];
    const float* kb = k + base;
#pragma unroll
    for (int t = 0; t < 10; ++t) {
        const int j = j0 + i0l + t;
        const bool valid = (j >= 0) && (j < SEQ);
        float4 k0 = make_float4(0.f, 0.f, 0.f, 0.f);
        float4 k1 = k0;
        if (valid) {
            const float4* kr = (const float4*)(kb + (size_t)j * DMODEL);
            k0 = kr[2 * s];
            k1 = kr[2 * s + 1];
        }
        if (t < 9) {
            float d = dot4(qa0, k0) + dot4(qa1, k1);
            d += __shfl_xor_sync(0xffffffffu, d, 1);
            d += __shfl_xor_sync(0xffffffffu, d, 2);
            d += __shfl_xor_sync(0xffffffffu, d, 4);
            w0[t] = valid ? d * SCALE : -CUDART_INF_F;
        }
        if (t > 0) {
            float d = dot4(qb0, k0) + dot4(qb1, k1);
            d += __shfl_xor_sync(0xffffffffu, d, 1);
            d += __shfl_xor_sync(0xffffffffu, d, 2);
            d += __shfl_xor_sync(0xffffffffu, d, 4);
            w1[t - 1] = valid ? d * SCALE : -CUDART_INF_F;
        }
    }

    // ---- Softmax over <=9 valid entries per query ----
    float m0 = -CUDART_INF_F, m1 = -CUDART_INF_F;
#pragma unroll
    for (int o = 0; o < BANDW; ++o) { m0 = fmaxf(m0, w0[o]); m1 = fmaxf(m1, w1[o]); }
    float sum0 = 0.f, sum1 = 0.f;
#pragma unroll
    for (int o = 0; o < BANDW; ++o) {
        w0[o] = __expf(w0[o] - m0); sum0 += w0[o];
        w1[o] = __expf(w1[o] - m1); sum1 += w1[o];
    }
    const float inv0 = 1.0f / sum0;
    const float inv1 = 1.0f / sum1;
#pragma unroll
    for (int o = 0; o < BANDW; ++o) { w0[o] *= inv0; w1[o] *= inv1; }

    // ---- Weighted V: 10 shared v rows serve both accumulators ----
    float4 a00 = make_float4(0.f, 0.f, 0.f, 0.f), a01 = a00;
    float4 a10 = a00, a11 = a00;
    const float* vb = v + base;
#pragma unroll
    for (int t = 0; t < 10; ++t) {
        const int j = j0 + i0l + t;
        float4 v0 = make_float4(0.f, 0.f, 0.f, 0.f);
        float4 v1 = v0;
        if (j >= 0 && j < SEQ) {
            const float4* vr = (const float4*)(vb + (size_t)j * DMODEL);
            v0 = vr[2 * s];
            v1 = vr[2 * s + 1];
        }
        if (t < 9) {
            const float w = w0[t];
            a00.x += w * v0.x; a00.y += w * v0.y; a00.z += w * v0.z; a00.w += w * v0.w;
            a01.x += w * v1.x; a01.y += w * v1.y; a01.z += w * v1.z; a01.w += w * v1.w;
        }
        if (t > 0) {
            const float w = w1[t - 1];
            a10.x += w * v0.x; a10.y += w * v0.y; a10.z += w * v0.z; a10.w += w * v0.w;
            a11.x += w * v1.x; a11.y += w * v1.y; a11.z += w * v1.z; a11.w += w * v1.w;
        }
    }

    float4* o0p = (float4*)(out + base + (size_t)i0 * DMODEL);
    float4* o1p = (float4*)(out + base + (size_t)i1 * DMODEL);
    o0p[2 * s]     = a00;
    o0p[2 * s + 1] = a01;
    o1p[2 * s]     = a10;
    o1p[2 * s + 1] = a11;
}

extern "C" void kernel_launch(void* const* d_in, const int* in_sizes, int n_in,
                              void* d_out, int out_size)
{
    const float* q = (const float*)d_in[0];
    const float* k = (const float*)d_in[1];
    const float* v = (const float*)d_in[2];
    float* out = (float*)d_out;

    dim3 grid(SEQ / QT, NHEADS, 256);   // (2, 16, 256)
    dim3 block(256);                    // 32 groups x 2 queries = 64 queries
    banded_attn_kernel<<<grid, block>>>(q, k, v, out);
}

// round 4
// speedup vs baseline: 2.6358x; 1.1874x over previous
#include <cuda_runtime.h>
#include <math_constants.h>

// Banded sparse attention, B=256, S=128, D=1024, H=16, Dh=64, |i-j|<=4.
// No smem: k/v rows are L1-cached. 8-lane group handles 4 consecutive
// queries sharing a 12-row band (3 rows loaded per query vs 5 before).
// Each lane owns 8 dims (2 float4). 3-shfl dot reductions.

#define SEQ    128
#define DMODEL 1024
#define NHEADS 16
#define HEADD  64
#define HW     4
#define BANDW  9
#define QPG    4              // queries per group
#define NT     (QPG + 2*HW)   // 12 band rows per group
#define QT     64             // queries per CTA (16 groups x 4)
#define SCALE  0.125f

__device__ __forceinline__ float dot4(const float4 a, const float4 b) {
    return a.x * b.x + a.y * b.y + a.z * b.z + a.w * b.w;
}

__device__ __forceinline__ void fma4(float4& a, float w, const float4 v) {
    a.x += w * v.x; a.y += w * v.y; a.z += w * v.z; a.w += w * v.w;
}

__global__ __launch_bounds__(128, 5)
void banded_attn_kernel(const float* __restrict__ q,
                        const float* __restrict__ k,
                        const float* __restrict__ v,
                        float* __restrict__ out)
{
    const int b   = blockIdx.z;
    const int h   = blockIdx.y;
    const int q0  = blockIdx.x * QT;
    const int tid = threadIdx.x;

    const int g   = tid >> 3;          // group 0..15
    const int s   = tid & 7;           // lane in group; owns float4 cols 2s, 2s+1
    const int i0  = q0 + g * QPG;      // first query of this group
    const int j0g = i0 - HW;           // first band row (may be <0)

    const size_t base = ((size_t)b * SEQ) * DMODEL + (size_t)h * HEADD;

    // ---- q rows for the 4 queries (8 dims per lane each) ----
    float4 qv[QPG][2];
#pragma unroll
    for (int m = 0; m < QPG; ++m) {
        const float4* qp = (const float4*)(q + base + (size_t)(i0 + m) * DMODEL);
        qv[m][0] = qp[2 * s];
        qv[m][1] = qp[2 * s + 1];
    }

    // ---- Scores: 12 shared k rows serve 4 queries; inline 3-shfl reduce ----
    float w[QPG][BANDW];
    const float* kb = k + base;
#pragma unroll
    for (int t = 0; t < NT; ++t) {
        const int j = j0g + t;
        const bool valid = (j >= 0) && (j < SEQ);
        float4 k0 = make_float4(0.f, 0.f, 0.f, 0.f);
        float4 k1 = k0;
        if (valid) {
            const float4* kr = (const float4*)(kb + (size_t)j * DMODEL);
            k0 = kr[2 * s];
            k1 = kr[2 * s + 1];
        }
#pragma unroll
        for (int m = 0; m < QPG; ++m) {
            if (t >= m && t <= m + 2 * HW) {           // compile-time
                float d = dot4(qv[m][0], k0) + dot4(qv[m][1], k1);
                d += __shfl_xor_sync(0xffffffffu, d, 1);
                d += __shfl_xor_sync(0xffffffffu, d, 2);
                d += __shfl_xor_sync(0xffffffffu, d, 4);
                w[m][t - m] = valid ? d * SCALE : -CUDART_INF_F;
            }
        }
    }

    // ---- Softmax per query over <=9 valid entries ----
#pragma unroll
    for (int m = 0; m < QPG; ++m) {
        float mx = -CUDART_INF_F;
#pragma unroll
        for (int o = 0; o < BANDW; ++o) mx = fmaxf(mx, w[m][o]);
        float sum = 0.f;
#pragma unroll
        for (int o = 0; o < BANDW; ++o) { w[m][o] = __expf(w[m][o] - mx); sum += w[m][o]; }
        const float inv = 1.0f / sum;
#pragma unroll
        for (int o = 0; o < BANDW; ++o) w[m][o] *= inv;
    }

    // ---- Weighted V: 12 shared v rows serve 4 accumulators ----
    float4 acc[QPG][2];
#pragma unroll
    for (int m = 0; m < QPG; ++m) {
        acc[m][0] = make_float4(0.f, 0.f, 0.f, 0.f);
        acc[m][1] = acc[m][0];
    }
    const float* vb = v + base;
#pragma unroll
    for (int t = 0; t < NT; ++t) {
        const int j = j0g + t;
        float4 v0 = make_float4(0.f, 0.f, 0.f, 0.f);
        float4 v1 = v0;
        if (j >= 0 && j < SEQ) {
            const float4* vr = (const float4*)(vb + (size_t)j * DMODEL);
            v0 = vr[2 * s];
            v1 = vr[2 * s + 1];
        }
#pragma unroll
        for (int m = 0; m < QPG; ++m) {
            if (t >= m && t <= m + 2 * HW) {           // compile-time
                const float wm = w[m][t - m];
                fma4(acc[m][0], wm, v0);
                fma4(acc[m][1], wm, v1);
            }
        }
    }

    // ---- Store ----
#pragma unroll
    for (int m = 0; m < QPG; ++m) {
        float4* op = (float4*)(out + base + (size_t)(i0 + m) * DMODEL);
        op[2 * s]     = acc[m][0];
        op[2 * s + 1] = acc[m][1];
    }
}

extern "C" void kernel_launch(void* const* d_in, const int* in_sizes, int n_in,
                              void* d_out, int out_size)
{
    const float* q = (const float*)d_in[0];
    const float* k = (const float*)d_in[1];
    const float* v = (const float*)d_in[2];
    float* out = (float*)d_out;

    dim3 grid(SEQ / QT, NHEADS, 256);   // (2, 16, 256)
    dim3 block(128);                    // 16 groups x 4 queries = 64 queries
    banded_attn_kernel<<<grid, block>>>(q, k, v, out);
}